// round 14
// baseline (speedup 1.0000x reference)
#include <cuda_runtime.h>
#include <cuda_bf16.h>
#include <cstdint>

#define BATCH 2
#define SEQ   2048
#define CDIM  1024
#define NH    16
#define HD    64
#define MROWS (BATCH * SEQ)      // 4096
#define F3    (3 * CDIM)         // 3072
#define NBH   (BATCH * NH)       // 32
// Q pre-scale: 1/sqrt(64) * log2(e)  (softmax done in exp2 domain)
#define QSCALE_LOG2 0.18033688011112042f

// ---------------------------------------------------------------------------
// Static scratch (allocation-free)
// ---------------------------------------------------------------------------
__device__ __nv_bfloat16 g_x_hi[(size_t)MROWS * CDIM];
__device__ __nv_bfloat16 g_x_lo[(size_t)MROWS * CDIM];
__device__ __nv_bfloat16 g_wqkv_hi[(size_t)F3 * CDIM];
__device__ __nv_bfloat16 g_wqkv_lo[(size_t)F3 * CDIM];
__device__ __nv_bfloat16 g_wout_hi[(size_t)CDIM * CDIM];
__device__ __nv_bfloat16 g_wout_lo[(size_t)CDIM * CDIM];
__device__ __nv_bfloat16 g_qkv_hi[(size_t)MROWS * F3];   // Q pre-scaled (log2 dom)
__device__ __nv_bfloat16 g_qkv_lo[(size_t)MROWS * F3];
__device__ __nv_bfloat16 g_attn_hi[(size_t)MROWS * CDIM];
__device__ __nv_bfloat16 g_attn_lo[(size_t)MROWS * CDIM];

// ---------------------------------------------------------------------------
// Helpers
// ---------------------------------------------------------------------------
__device__ __forceinline__ uint32_t smem_u32(const void* p) {
    uint32_t a;
    asm("{ .reg .u64 t; cvta.to.shared.u64 t, %1; cvt.u32.u64 %0, t; }"
        : "=r"(a) : "l"(p));
    return a;
}
__device__ __forceinline__ void cvt_hilo(float x, __nv_bfloat16& h, __nv_bfloat16& l) {
    h = __float2bfloat16(x);
    l = __float2bfloat16(x - __bfloat162float(h));
}
__device__ __forceinline__ uint32_t pk(__nv_bfloat16 a, __nv_bfloat16 b) {
    return (uint32_t)__bfloat16_as_ushort(a) | ((uint32_t)__bfloat16_as_ushort(b) << 16);
}

#define LDMX4(r0, r1, r2, r3, addr)                                            \
    asm volatile("ldmatrix.sync.aligned.m8n8.x4.shared.b16 {%0,%1,%2,%3}, [%4];" \
                 : "=r"(r0), "=r"(r1), "=r"(r2), "=r"(r3) : "r"(addr))
#define LDMX4T(r0, r1, r2, r3, addr)                                           \
    asm volatile("ldmatrix.sync.aligned.m8n8.x4.trans.shared.b16 {%0,%1,%2,%3}, [%4];" \
                 : "=r"(r0), "=r"(r1), "=r"(r2), "=r"(r3) : "r"(addr))

__device__ __forceinline__ void mma16816(float* c, uint32_t a0, uint32_t a1,
                                         uint32_t a2, uint32_t a3,
                                         uint32_t b0, uint32_t b1) {
    asm volatile(
        "mma.sync.aligned.m16n8k16.row.col.f32.bf16.bf16.f32 "
        "{%0,%1,%2,%3}, {%4,%5,%6,%7}, {%8,%9}, {%0,%1,%2,%3};"
        : "+f"(c[0]), "+f"(c[1]), "+f"(c[2]), "+f"(c[3])
        : "r"(a0), "r"(a1), "r"(a2), "r"(a3), "r"(b0), "r"(b1));
}

#define CP16(dst, src) \
    asm volatile("cp.async.cg.shared.global [%0], [%1], 16;" :: "r"(dst), "l"(src))
#define CP_COMMIT() asm volatile("cp.async.commit_group;" ::: "memory")
#define CP_WAIT1()  asm volatile("cp.async.wait_group 1;" ::: "memory")
#define CP_WAIT0()  asm volatile("cp.async.wait_group 0;" ::: "memory")

// ============================ GEMM kernel ==================================
// CTA 128x128, 4 warps (2x2), warp tile 64x64, BK=32, double-buffered.
// smem/stage: A hi/lo + B hi/lo, 128 rows x 80B each => 40960B; 2 stages = 80KB
// => 2 CTAs/SM.
#define GM_ST   80
#define GM_T    10240             // 128 * 80
#define GM_BUF  40960             // [A_HI][A_LO][B_HI][B_LO]

__global__ void __launch_bounds__(128) mma_gemm(int mode,
                                                const float* __restrict__ bias,
                                                float* __restrict__ outp)
{
    extern __shared__ char smem[];
    const int tid  = threadIdx.x;
    const int wid  = tid >> 5, lane = tid & 31;
    const int m0   = (wid >> 1) * 64;    // 0 or 64
    const int n0   = (wid & 1) * 64;     // 0 or 64
    const uint32_t sb = smem_u32(smem);

    const int bm = blockIdx.y * 128, bn = blockIdx.x * 128;

    const __nv_bfloat16 *ahi, *alo, *bhi, *blo;
    if (mode == 0) {
        ahi = g_x_hi + (size_t)bm * CDIM;    alo = g_x_lo + (size_t)bm * CDIM;
        bhi = g_wqkv_hi + (size_t)bn * CDIM; blo = g_wqkv_lo + (size_t)bn * CDIM;
    } else {
        ahi = g_attn_hi + (size_t)bm * CDIM; alo = g_attn_lo + (size_t)bm * CDIM;
        bhi = g_wout_hi + (size_t)bn * CDIM; blo = g_wout_lo + (size_t)bn * CDIM;
    }

    auto cp_ab = [&](int buf, int k0) {
        uint32_t base = sb + (uint32_t)buf * GM_BUF;
#pragma unroll
        for (int it = 0; it < 8; ++it) {     // A: 1024 16B chunks
            int idx = tid + 128 * it;
            int mat = idx >> 9, r = (idx >> 2) & 127, c = idx & 3;
            uint32_t dst = base + (uint32_t)(mat * GM_T + r * GM_ST + c * 16);
            const __nv_bfloat16* src = (mat ? alo : ahi) + (size_t)r * CDIM + k0 + c * 8;
            CP16(dst, src);
        }
#pragma unroll
        for (int it = 0; it < 8; ++it) {     // B: 1024 16B chunks
            int idx = tid + 128 * it;
            int mat = idx >> 9, r = (idx >> 2) & 127, c = idx & 3;
            uint32_t dst = base + (uint32_t)(2 * GM_T + mat * GM_T + r * GM_ST + c * 16);
            const __nv_bfloat16* src = (mat ? blo : bhi) + (size_t)r * CDIM + k0 + c * 8;
            CP16(dst, src);
        }
    };

    float acc[4][8][4];
#pragma unroll
    for (int i = 0; i < 4; ++i)
#pragma unroll
        for (int j = 0; j < 8; ++j)
#pragma unroll
            for (int k = 0; k < 4; ++k) acc[i][j][k] = 0.0f;

    const int nt = CDIM / 32;   // 32 k-steps
    cp_ab(0, 0); CP_COMMIT();

    const uint32_t arow = (uint32_t)((m0 + (lane & 15)) * GM_ST + (lane >> 4) * 16);
    const uint32_t brow = (uint32_t)((n0 + 8 * (lane >> 4) + (lane & 7)) * GM_ST
                                     + ((lane >> 3) & 1) * 16);

    for (int t = 0; t < nt; ++t) {
        const int bf = t & 1;
        if (t + 1 < nt) {
            cp_ab(1 - bf, (t + 1) * 32);
            CP_COMMIT();
            CP_WAIT1();
        } else {
            CP_WAIT0();
        }
        __syncthreads();

        const uint32_t aH = sb + (uint32_t)bf * GM_BUF;
        const uint32_t aL = aH + GM_T;
        const uint32_t bH = aH + 2 * GM_T;
        const uint32_t bL = aH + 3 * GM_T;

#pragma unroll
        for (int ks = 0; ks < 2; ++ks) {
            const uint32_t kadd = (uint32_t)(ks * 32);
            uint32_t ah[4][4], al[4][4];
#pragma unroll
            for (int i = 0; i < 4; ++i) {
                uint32_t ao = arow + (uint32_t)(i * 16 * GM_ST) + kadd;
                LDMX4(ah[i][0], ah[i][1], ah[i][2], ah[i][3], aH + ao);
                LDMX4(al[i][0], al[i][1], al[i][2], al[i][3], aL + ao);
            }
            uint32_t bh[8][2], bl[8][2];
#pragma unroll
            for (int jj = 0; jj < 4; ++jj) {
                uint32_t bo = brow + (uint32_t)(jj * 16 * GM_ST) + kadd;
                LDMX4(bh[2*jj][0], bh[2*jj][1], bh[2*jj+1][0], bh[2*jj+1][1], bH + bo);
                LDMX4(bl[2*jj][0], bl[2*jj][1], bl[2*jj+1][0], bl[2*jj+1][1], bL + bo);
            }
#pragma unroll
            for (int i = 0; i < 4; ++i)
#pragma unroll
                for (int j = 0; j < 8; ++j) {
                    float* a = acc[i][j];
                    mma16816(a, ah[i][0], ah[i][1], ah[i][2], ah[i][3],
                             bh[j][0], bh[j][1]);
                    mma16816(a, ah[i][0], ah[i][1], ah[i][2], ah[i][3],
                             bl[j][0], bl[j][1]);
                    mma16816(a, al[i][0], al[i][1], al[i][2], al[i][3],
                             bh[j][0], bh[j][1]);
                }
        }
        __syncthreads();
    }

    if (mode == 2) {
#pragma unroll
        for (int i = 0; i < 4; ++i) {
            const int r0 = bm + m0 + 16 * i + (lane >> 2);
#pragma unroll
            for (int j = 0; j < 8; ++j) {
                const int col = bn + n0 + 8 * j + (lane & 3) * 2;
                float b0 = bias[col], b1 = bias[col + 1];
                *(float2*)(outp + (size_t)r0 * CDIM + col) =
                    make_float2(acc[i][j][0] + b0, acc[i][j][1] + b1);
                *(float2*)(outp + (size_t)(r0 + 8) * CDIM + col) =
                    make_float2(acc[i][j][2] + b0, acc[i][j][3] + b1);
            }
        }
    } else {
        // QKV epilogue: Q region (cols < 1024) pre-scaled into exp2 domain
        const float scale = ((bn + n0) < CDIM) ? QSCALE_LOG2 : 1.0f;
#pragma unroll
        for (int i = 0; i < 4; ++i) {
            const int r0 = bm + m0 + 16 * i + (lane >> 2);
#pragma unroll
            for (int j = 0; j < 8; ++j) {
                const int col = bn + n0 + 8 * j + (lane & 3) * 2;
                __nv_bfloat16 h0, h1, l0, l1;
#pragma unroll
                for (int half = 0; half < 2; ++half) {
                    cvt_hilo(acc[i][j][2 * half + 0] * scale, h0, l0);
                    cvt_hilo(acc[i][j][2 * half + 1] * scale, h1, l1);
                    const size_t off = (size_t)(r0 + 8 * half) * F3 + col;
                    *(uint32_t*)(g_qkv_hi + off) = pk(h0, h1);
                    *(uint32_t*)(g_qkv_lo + off) = pk(l0, l1);
                }
            }
        }
    }
}

// ======================= Fused flash attention =============================
// Per CTA: 64 q-rows of one (b,h), 4 warps (16 rows each). 64-key tiles,
// K & V cp.async row-major; V B-fragments via ldmatrix.trans.
// smem: Q hi/lo 18KB + K dbl hi/lo 36KB + V dbl hi/lo 36KB = 90KB => 2 CTA/SM
#define FL_STRIDE 144
#define FL_Q      9216               // 64*144
#define FL_KV     9216
#define FL_KBASE  (2 * FL_Q)         // 18432
#define FL_VBASE  (FL_KBASE + 4 * FL_KV)  // 55296
#define FL_SMEM   (FL_VBASE + 4 * FL_KV)  // 92160

__global__ void __launch_bounds__(128) flash_kernel()
{
    extern __shared__ char smem[];
    const int tid = threadIdx.x, wid = tid >> 5, lane = tid & 31;
    const uint32_t sb = smem_u32(smem);
    const int z = blockIdx.y, b = z >> 4, h = z & 15;
    const int bm = blockIdx.x * 64;
    const int wm = wid * 16;

    const size_t qoff = (size_t)(b * SEQ + bm) * F3 + (size_t)h * HD;
    const __nv_bfloat16* qhg = g_qkv_hi + qoff;
    const __nv_bfloat16* qlg = g_qkv_lo + qoff;
    const size_t kbase = (size_t)b * SEQ * F3 + CDIM + (size_t)h * HD;
    const __nv_bfloat16* khg = g_qkv_hi + kbase;
    const __nv_bfloat16* klg = g_qkv_lo + kbase;
    const size_t vbase = (size_t)b * SEQ * F3 + 2 * CDIM + (size_t)h * HD;
    const __nv_bfloat16* vhg = g_qkv_hi + vbase;
    const __nv_bfloat16* vlg = g_qkv_lo + vbase;

    const uint32_t SQH = sb, SQL = sb + FL_Q;

    // Q (group 0): 64 rows x 64 cols hi+lo = 1024 chunks
#pragma unroll
    for (int it = 0; it < 8; ++it) {
        int idx = tid + 128 * it;
        int mat = idx >> 9, r = (idx >> 3) & 63, c = idx & 7;
        uint32_t dst = (mat ? SQL : SQH) + (uint32_t)(r * FL_STRIDE + c * 16);
        const __nv_bfloat16* src = (mat ? qlg : qhg) + (size_t)r * F3 + c * 8;
        CP16(dst, src);
    }
    CP_COMMIT();

    auto cp_k = [&](int buf, int key0) {
        uint32_t base = sb + FL_KBASE + (uint32_t)buf * 2 * FL_KV;
#pragma unroll
        for (int it = 0; it < 8; ++it) {
            int idx = tid + 128 * it;
            int mat = idx >> 9, r = (idx >> 3) & 63, c = idx & 7;
            uint32_t dst = base + (uint32_t)(mat * FL_KV + r * FL_STRIDE + c * 16);
            const __nv_bfloat16* src = (mat ? klg : khg) + (size_t)(key0 + r) * F3 + c * 8;
            CP16(dst, src);
        }
    };
    auto cp_v = [&](int buf, int key0) {
        uint32_t base = sb + FL_VBASE + (uint32_t)buf * 2 * FL_KV;
#pragma unroll
        for (int it = 0; it < 8; ++it) {
            int idx = tid + 128 * it;
            int mat = idx >> 9, r = (idx >> 3) & 63, c = idx & 7;
            uint32_t dst = base + (uint32_t)(mat * FL_KV + r * FL_STRIDE + c * 16);
            const __nv_bfloat16* src = (mat ? vlg : vhg) + (size_t)(key0 + r) * F3 + c * 8;
            CP16(dst, src);
        }
    };

    cp_k(0, 0); cp_v(0, 0); CP_COMMIT();
    CP_WAIT1();                       // Q resident
    __syncthreads();

    // Q fragments (resident; pre-scaled into exp2 domain)
    uint32_t qh[4][4], ql[4][4];
    {
        const uint32_t arow = (uint32_t)((wm + (lane & 15)) * FL_STRIDE + (lane >> 4) * 16);
#pragma unroll
        for (int ks = 0; ks < 4; ++ks) {
            LDMX4(qh[ks][0], qh[ks][1], qh[ks][2], qh[ks][3], SQH + arow + ks * 32);
            LDMX4(ql[ks][0], ql[ks][1], ql[ks][2], ql[ks][3], SQL + arow + ks * 32);
        }
    }

    float acco[8][4];
#pragma unroll
    for (int j = 0; j < 8; ++j)
#pragma unroll
        for (int k = 0; k < 4; ++k) acco[j][k] = 0.0f;
    float mr0 = -1e30f, mr1 = -1e30f, lr0 = 0.0f, lr1 = 0.0f;

    const uint32_t boff = (uint32_t)((8 * (lane >> 4) + (lane & 7)) * FL_STRIDE
                                     + ((lane >> 3) & 1) * 16);
    const uint32_t voff = (uint32_t)(((((lane >> 3) & 1) * 8) + (lane & 7)) * FL_STRIDE
                                     + (lane >> 4) * 16);

    const int NT = SEQ / 64;  // 32
    for (int t = 0; t < NT; ++t) {
        const int bf = t & 1;
        if (t + 1 < NT) {
            cp_k(1 - bf, (t + 1) * 64);
            cp_v(1 - bf, (t + 1) * 64);
            CP_COMMIT();
            CP_WAIT1();
        } else {
            CP_WAIT0();
        }
        __syncthreads();

        // ---- S = Q @ K^T (3-pass); S already in log2 units
        const uint32_t khb = sb + FL_KBASE + (uint32_t)bf * 2 * FL_KV;
        const uint32_t klb = khb + FL_KV;
        float accs[8][4];
#pragma unroll
        for (int j = 0; j < 8; ++j)
#pragma unroll
            for (int k = 0; k < 4; ++k) accs[j][k] = 0.0f;
#pragma unroll
        for (int ks = 0; ks < 4; ++ks) {
#pragma unroll
            for (int jp = 0; jp < 4; ++jp) {
                uint32_t off = boff + (uint32_t)(jp * 16 * FL_STRIDE + ks * 32);
                uint32_t h0, h1, h2, h3, e0, e1, e2, e3;
                LDMX4(h0, h1, h2, h3, khb + off);
                LDMX4(e0, e1, e2, e3, klb + off);
                mma16816(accs[2*jp],   qh[ks][0], qh[ks][1], qh[ks][2], qh[ks][3], h0, h1);
                mma16816(accs[2*jp+1], qh[ks][0], qh[ks][1], qh[ks][2], qh[ks][3], h2, h3);
                mma16816(accs[2*jp],   qh[ks][0], qh[ks][1], qh[ks][2], qh[ks][3], e0, e1);
                mma16816(accs[2*jp+1], qh[ks][0], qh[ks][1], qh[ks][2], qh[ks][3], e2, e3);
                mma16816(accs[2*jp],   ql[ks][0], ql[ks][1], ql[ks][2], ql[ks][3], h0, h1);
                mma16816(accs[2*jp+1], ql[ks][0], ql[ks][1], ql[ks][2], ql[ks][3], h2, h3);
            }
        }

        // ---- online softmax (exp2 domain)
        float rm0 = -1e30f, rm1 = -1e30f;
#pragma unroll
        for (int j = 0; j < 8; ++j) {
            rm0 = fmaxf(rm0, fmaxf(accs[j][0], accs[j][1]));
            rm1 = fmaxf(rm1, fmaxf(accs[j][2], accs[j][3]));
        }
        rm0 = fmaxf(rm0, __shfl_xor_sync(0xffffffffu, rm0, 1));
        rm0 = fmaxf(rm0, __shfl_xor_sync(0xffffffffu, rm0, 2));
        rm1 = fmaxf(rm1, __shfl_xor_sync(0xffffffffu, rm1, 1));
        rm1 = fmaxf(rm1, __shfl_xor_sync(0xffffffffu, rm1, 2));
        const float mn0 = fmaxf(mr0, rm0), mn1 = fmaxf(mr1, rm1);
        const float al0 = exp2f(mr0 - mn0), al1 = exp2f(mr1 - mn1);
        mr0 = mn0; mr1 = mn1;

        float s0 = 0.0f, s1 = 0.0f;
        uint32_t pah[4][4], pal[4][4];
#pragma unroll
        for (int j = 0; j < 8; ++j) {
            float p0 = exp2f(accs[j][0] - mn0);
            float p1 = exp2f(accs[j][1] - mn0);
            float p2 = exp2f(accs[j][2] - mn1);
            float p3 = exp2f(accs[j][3] - mn1);
            s0 += p0 + p1; s1 += p2 + p3;
            __nv_bfloat16 h0b, l0b, h1b, l1b, h2b, l2b, h3b, l3b;
            cvt_hilo(p0, h0b, l0b); cvt_hilo(p1, h1b, l1b);
            cvt_hilo(p2, h2b, l2b); cvt_hilo(p3, h3b, l3b);
            const int ks = j >> 1;
            if ((j & 1) == 0) {
                pah[ks][0] = pk(h0b, h1b); pah[ks][1] = pk(h2b, h3b);
                pal[ks][0] = pk(l0b, l1b); pal[ks][1] = pk(l2b, l3b);
            } else {
                pah[ks][2] = pk(h0b, h1b); pah[ks][3] = pk(h2b, h3b);
                pal[ks][2] = pk(l0b, l1b); pal[ks][3] = pk(l2b, l3b);
            }
        }
        s0 += __shfl_xor_sync(0xffffffffu, s0, 1);
        s0 += __shfl_xor_sync(0xffffffffu, s0, 2);
        s1 += __shfl_xor_sync(0xffffffffu, s1, 1);
        s1 += __shfl_xor_sync(0xffffffffu, s1, 2);
        lr0 = lr0 * al0 + s0; lr1 = lr1 * al1 + s1;
#pragma unroll
        for (int j = 0; j < 8; ++j) {
            acco[j][0] *= al0; acco[j][1] *= al0;
            acco[j][2] *= al1; acco[j][3] *= al1;
        }

        // ---- O += P @ V (3-pass); V fragments via ldmatrix.trans
        const uint32_t vhb = sb + FL_VBASE + (uint32_t)bf * 2 * FL_KV;
        const uint32_t vlb = vhb + FL_KV;
#pragma unroll
        for (int ks = 0; ks < 4; ++ks) {
#pragma unroll
            for (int jp = 0; jp < 4; ++jp) {
                uint32_t off = voff + (uint32_t)(ks * 16 * FL_STRIDE + jp * 32);
                uint32_t h0, h1, h2, h3, e0, e1, e2, e3;
                LDMX4T(h0, h1, h2, h3, vhb + off);
                LDMX4T(e0, e1, e2, e3, vlb + off);
                mma16816(acco[2*jp],   pah[ks][0], pah[ks][1], pah[ks][2], pah[ks][3], h0, h1);
                mma16816(acco[2*jp+1], pah[ks][0], pah[ks][1], pah[ks][2], pah[ks][3], h2, h3);
                mma16816(acco[2*jp],   pah[ks][0], pah[ks][1], pah[ks][2], pah[ks][3], e0, e1);
                mma16816(acco[2*jp+1], pah[ks][0], pah[ks][1], pah[ks][2], pah[ks][3], e2, e3);
                mma16816(acco[2*jp],   pal[ks][0], pal[ks][1], pal[ks][2], pal[ks][3], h0, h1);
                mma16816(acco[2*jp+1], pal[ks][0], pal[ks][1], pal[ks][2], pal[ks][3], h2, h3);
            }
        }
        __syncthreads();
    }

    // ---- epilogue: O / l -> attn hi/lo
    const float inv0 = 1.0f / lr0, inv1 = 1.0f / lr1;
    const int rg = b * SEQ + bm + wm + (lane >> 2);
#pragma unroll
    for (int j = 0; j < 8; ++j) {
        const int col = h * HD + j * 8 + (lane & 3) * 2;
        __nv_bfloat16 h0b, l0b, h1b, l1b;
        cvt_hilo(acco[j][0] * inv0, h0b, l0b);
        cvt_hilo(acco[j][1] * inv0, h1b, l1b);
        size_t off = (size_t)rg * CDIM + col;
        *(uint32_t*)(g_attn_hi + off) = pk(h0b, h1b);
        *(uint32_t*)(g_attn_lo + off) = pk(l0b, l1b);
        cvt_hilo(acco[j][2] * inv1, h0b, l0b);
        cvt_hilo(acco[j][3] * inv1, h1b, l1b);
        off = (size_t)(rg + 8) * CDIM + col;
        *(uint32_t*)(g_attn_hi + off) = pk(h0b, h1b);
        *(uint32_t*)(g_attn_lo + off) = pk(l0b, l1b);
    }
}

// ---------------------------------------------------------------------------
// fp32 -> bf16 hi/lo elementwise convert
// ---------------------------------------------------------------------------
__global__ void __launch_bounds__(256) cvt_kernel(
    const float4* __restrict__ src, uint2* __restrict__ hi,
    uint2* __restrict__ lo, int n4)
{
    int i = blockIdx.x * blockDim.x + threadIdx.x;
    if (i >= n4) return;
    float4 v = src[i];
    __nv_bfloat16 h0, h1, h2, h3, l0, l1, l2, l3;
    cvt_hilo(v.x, h0, l0); cvt_hilo(v.y, h1, l1);
    cvt_hilo(v.z, h2, l2); cvt_hilo(v.w, h3, l3);
    hi[i] = make_uint2(pk(h0, h1), pk(h2, h3));
    lo[i] = make_uint2(pk(l0, l1), pk(l2, l3));
}

// ---------------------------------------------------------------------------
extern "C" void kernel_launch(void* const* d_in, const int* in_sizes, int n_in,
                              void* d_out, int out_size)
{
    (void)in_sizes; (void)n_in; (void)out_size;
    const float* x     = (const float*)d_in[0];
    const float* w_qkv = (const float*)d_in[1];
    const float* w_out = (const float*)d_in[2];
    const float* b_out = (const float*)d_in[3];
    float* out = (float*)d_out;

    static int attr_done = 0;
    if (!attr_done) {
        cudaFuncSetAttribute(mma_gemm, cudaFuncAttributeMaxDynamicSharedMemorySize,
                             2 * GM_BUF);
        cudaFuncSetAttribute(flash_kernel, cudaFuncAttributeMaxDynamicSharedMemorySize,
                             FL_SMEM);
        attr_done = 1;
    }

    __nv_bfloat16 *xh, *xl, *qh, *ql, *oh, *ol;
    cudaGetSymbolAddress((void**)&xh, g_x_hi);
    cudaGetSymbolAddress((void**)&xl, g_x_lo);
    cudaGetSymbolAddress((void**)&qh, g_wqkv_hi);
    cudaGetSymbolAddress((void**)&ql, g_wqkv_lo);
    cudaGetSymbolAddress((void**)&oh, g_wout_hi);
    cudaGetSymbolAddress((void**)&ol, g_wout_lo);

    {
        int n4 = MROWS * CDIM / 4;
        cvt_kernel<<<(n4 + 255) / 256, 256>>>((const float4*)x, (uint2*)xh, (uint2*)xl, n4);
        n4 = F3 * CDIM / 4;
        cvt_kernel<<<(n4 + 255) / 256, 256>>>((const float4*)w_qkv, (uint2*)qh, (uint2*)ql, n4);
        n4 = CDIM * CDIM / 4;
        cvt_kernel<<<(n4 + 255) / 256, 256>>>((const float4*)w_out, (uint2*)oh, (uint2*)ol, n4);
    }

    // 1) QKV -> g_qkv hi/lo (Q pre-scaled into exp2 domain)
    mma_gemm<<<dim3(F3 / 128, MROWS / 128), 128, 2 * GM_BUF>>>(0, nullptr, nullptr);
    // 2) fused flash attention -> g_attn hi/lo
    flash_kernel<<<dim3(SEQ / 64, NBH), 128, FL_SMEM>>>();
    // 3) proj -> out (+bias)
    mma_gemm<<<dim3(CDIM / 128, MROWS / 128), 128, 2 * GM_BUF>>>(2, b_out, out);
}

// round 17
// speedup vs baseline: 2.2041x; 2.2041x over previous
#include <cuda_runtime.h>
#include <cuda_fp16.h>
#include <cstdint>

#define BATCH 2
#define SEQ   2048
#define CDIM  1024
#define NH    16
#define HD    64
#define MROWS (BATCH * SEQ)      // 4096
#define F3    (3 * CDIM)         // 3072
#define NBH   (BATCH * NH)       // 32
// Q pre-scale: 1/sqrt(64) * log2(e)  (softmax in exp2 domain)
#define QSCALE_LOG2 0.18033688011112042f

// ---------------------------------------------------------------------------
// Static scratch (allocation-free). A-side operands keep hi+lo; B-side hi only.
// ---------------------------------------------------------------------------
__device__ __half g_x_hi[(size_t)MROWS * CDIM];
__device__ __half g_x_lo[(size_t)MROWS * CDIM];
__device__ __half g_wqkv_hi[(size_t)F3 * CDIM];      // B: hi only used
__device__ __half g_wout_hi[(size_t)CDIM * CDIM];    // B: hi only used
__device__ __half g_qkv_hi[(size_t)MROWS * F3];      // Q pre-scaled (log2 dom)
__device__ __half g_qkv_lo[(size_t)MROWS * F3];      // lo used only for Q cols
__device__ __half g_attn_hi[(size_t)MROWS * CDIM];
__device__ __half g_attn_lo[(size_t)MROWS * CDIM];

// ---------------------------------------------------------------------------
// Helpers
// ---------------------------------------------------------------------------
__device__ __forceinline__ uint32_t smem_u32(const void* p) {
    uint32_t a;
    asm("{ .reg .u64 t; cvta.to.shared.u64 t, %1; cvt.u32.u64 %0, t; }"
        : "=r"(a) : "l"(p));
    return a;
}
__device__ __forceinline__ void cvt_hilo(float x, __half& h, __half& l) {
    h = __float2half_rn(x);
    l = __float2half_rn(x - __half2float(h));
}
__device__ __forceinline__ uint32_t pk(__half a, __half b) {
    return (uint32_t)__half_as_ushort(a) | ((uint32_t)__half_as_ushort(b) << 16);
}

#define LDMX4(r0, r1, r2, r3, addr)                                            \
    asm volatile("ldmatrix.sync.aligned.m8n8.x4.shared.b16 {%0,%1,%2,%3}, [%4];" \
                 : "=r"(r0), "=r"(r1), "=r"(r2), "=r"(r3) : "r"(addr))
#define LDMX4T(r0, r1, r2, r3, addr)                                           \
    asm volatile("ldmatrix.sync.aligned.m8n8.x4.trans.shared.b16 {%0,%1,%2,%3}, [%4];" \
                 : "=r"(r0), "=r"(r1), "=r"(r2), "=r"(r3) : "r"(addr))

__device__ __forceinline__ void mma16816(float* c, uint32_t a0, uint32_t a1,
                                         uint32_t a2, uint32_t a3,
                                         uint32_t b0, uint32_t b1) {
    asm volatile(
        "mma.sync.aligned.m16n8k16.row.col.f32.f16.f16.f32 "
        "{%0,%1,%2,%3}, {%4,%5,%6,%7}, {%8,%9}, {%0,%1,%2,%3};"
        : "+f"(c[0]), "+f"(c[1]), "+f"(c[2]), "+f"(c[3])
        : "r"(a0), "r"(a1), "r"(a2), "r"(a3), "r"(b0), "r"(b1));
}

#define CP16(dst, src) \
    asm volatile("cp.async.cg.shared.global [%0], [%1], 16;" :: "r"(dst), "l"(src))
#define CP_COMMIT() asm volatile("cp.async.commit_group;" ::: "memory")
#define CP_WAIT1()  asm volatile("cp.async.wait_group 1;" ::: "memory")
#define CP_WAIT0()  asm volatile("cp.async.wait_group 0;" ::: "memory")

// ============================ GEMM kernel ==================================
// CTA tile 128(M) x 256(N), BK=64, 8 warps (2x4), warp tile 64x64.
// 2-pass fp16: Ah*Bh + Al*Bh (B hi only). Double-buffered.
// Stage: A hi/lo 2*18432 + B hi 36864 = 73728; x2 = 147456 (1 CTA/SM).
#define GM_ST    144
#define GM_A     18432            // 128 * 144
#define GM_B     36864            // 256 * 144
#define GM_BUF   (2 * GM_A + GM_B)    // 73728

__global__ void __launch_bounds__(256) mma_gemm(int mode,
                                                const float* __restrict__ bias,
                                                float* __restrict__ outp)
{
    extern __shared__ char smem[];
    const int tid  = threadIdx.x;
    const int wid  = tid >> 5, lane = tid & 31;
    const int m0   = (wid >> 2) * 64;    // 0 or 64
    const int n0   = (wid & 3) * 64;     // 0,64,128,192
    const uint32_t sb = smem_u32(smem);

    const int bm = blockIdx.y * 128, bn = blockIdx.x * 256;

    const __half *ahi, *alo, *bhi;
    if (mode == 0) {
        ahi = g_x_hi + (size_t)bm * CDIM;    alo = g_x_lo + (size_t)bm * CDIM;
        bhi = g_wqkv_hi + (size_t)bn * CDIM;
    } else {
        ahi = g_attn_hi + (size_t)bm * CDIM; alo = g_attn_lo + (size_t)bm * CDIM;
        bhi = g_wout_hi + (size_t)bn * CDIM;
    }

    auto cp_a = [&](int buf, int k0) {
        uint32_t base = sb + (uint32_t)buf * GM_BUF;
#pragma unroll
        for (int it = 0; it < 8; ++it) {
            int idx = tid + 256 * it;            // 0..2047
            int mat = idx >> 10, r = (idx >> 3) & 127, c = idx & 7;
            uint32_t dst = base + (uint32_t)(mat * GM_A + r * GM_ST + c * 16);
            const __half* src = (mat ? alo : ahi) + (size_t)r * CDIM + k0 + c * 8;
            CP16(dst, src);
        }
    };
    auto cp_b = [&](int buf, int k0) {
        uint32_t base = sb + (uint32_t)buf * GM_BUF + 2 * GM_A;
#pragma unroll
        for (int it = 0; it < 8; ++it) {
            int idx = tid + 256 * it;            // 0..2047
            int r = idx >> 3, c = idx & 7;
            uint32_t dst = base + (uint32_t)(r * GM_ST + c * 16);
            const __half* src = bhi + (size_t)r * CDIM + k0 + c * 8;
            CP16(dst, src);
        }
    };

    float acc[4][8][4];
#pragma unroll
    for (int i = 0; i < 4; ++i)
#pragma unroll
        for (int j = 0; j < 8; ++j)
#pragma unroll
            for (int k = 0; k < 4; ++k) acc[i][j][k] = 0.0f;

    const int nt = CDIM / 64;   // 16
    cp_a(0, 0); cp_b(0, 0); CP_COMMIT();

    const uint32_t arow = (uint32_t)((m0 + (lane & 15)) * GM_ST + (lane >> 4) * 16);
    const uint32_t brow = (uint32_t)((n0 + 8 * (lane >> 4) + (lane & 7)) * GM_ST
                                     + ((lane >> 3) & 1) * 16);

    for (int t = 0; t < nt; ++t) {
        const int bf = t & 1;
        if (t + 1 < nt) {
            const int nb = 1 - bf, k0 = (t + 1) * 64;
            cp_a(nb, k0); cp_b(nb, k0); CP_COMMIT();
            CP_WAIT1();
        } else {
            CP_WAIT0();
        }
        __syncthreads();

        const uint32_t aH = sb + (uint32_t)bf * GM_BUF;
        const uint32_t aL = aH + GM_A;
        const uint32_t bH = aH + 2 * GM_A;

#pragma unroll
        for (int ks = 0; ks < 4; ++ks) {
            const uint32_t kadd = (uint32_t)(ks * 32);
            uint32_t ah[4][4], al[4][4];
#pragma unroll
            for (int i = 0; i < 4; ++i) {
                uint32_t ao = arow + (uint32_t)(i * 16 * GM_ST) + kadd;
                LDMX4(ah[i][0], ah[i][1], ah[i][2], ah[i][3], aH + ao);
                LDMX4(al[i][0], al[i][1], al[i][2], al[i][3], aL + ao);
            }
#pragma unroll
            for (int half = 0; half < 2; ++half) {
                uint32_t bh[4][2];
#pragma unroll
                for (int jj = 0; jj < 2; ++jj) {
                    uint32_t bo = brow + (uint32_t)((half * 32 + jj * 16) * GM_ST) + kadd;
                    LDMX4(bh[2*jj][0], bh[2*jj][1], bh[2*jj+1][0], bh[2*jj+1][1], bH + bo);
                }
#pragma unroll
                for (int i = 0; i < 4; ++i)
#pragma unroll
                    for (int j = 0; j < 4; ++j) {
                        float* a = acc[i][half * 4 + j];
                        mma16816(a, ah[i][0], ah[i][1], ah[i][2], ah[i][3],
                                 bh[j][0], bh[j][1]);
                        mma16816(a, al[i][0], al[i][1], al[i][2], al[i][3],
                                 bh[j][0], bh[j][1]);
                    }
            }
        }
        __syncthreads();
    }

    if (mode == 2) {
#pragma unroll
        for (int i = 0; i < 4; ++i) {
            const int r0 = bm + m0 + 16 * i + (lane >> 2);
#pragma unroll
            for (int j = 0; j < 8; ++j) {
                const int col = bn + n0 + 8 * j + (lane & 3) * 2;
                float b0 = bias[col], b1 = bias[col + 1];
                *(float2*)(outp + (size_t)r0 * CDIM + col) =
                    make_float2(acc[i][j][0] + b0, acc[i][j][1] + b1);
                *(float2*)(outp + (size_t)(r0 + 8) * CDIM + col) =
                    make_float2(acc[i][j][2] + b0, acc[i][j][3] + b1);
            }
        }
    } else {
        // QKV epilogue. Q region (cols < 1024): pre-scale into exp2 domain,
        // write hi+lo. K/V regions: hi only (lo never read).
        const bool isQ = (bn + n0) < CDIM;
        const float scale = isQ ? QSCALE_LOG2 : 1.0f;
#pragma unroll
        for (int i = 0; i < 4; ++i) {
            const int r0 = bm + m0 + 16 * i + (lane >> 2);
#pragma unroll
            for (int j = 0; j < 8; ++j) {
                const int col = bn + n0 + 8 * j + (lane & 3) * 2;
                __half h0, h1, l0, l1;
#pragma unroll
                for (int half = 0; half < 2; ++half) {
                    cvt_hilo(acc[i][j][2 * half + 0] * scale, h0, l0);
                    cvt_hilo(acc[i][j][2 * half + 1] * scale, h1, l1);
                    const size_t off = (size_t)(r0 + 8 * half) * F3 + col;
                    *(uint32_t*)(g_qkv_hi + off) = pk(h0, h1);
                    if (isQ) *(uint32_t*)(g_qkv_lo + off) = pk(l0, l1);
                }
            }
        }
    }
}

// ======================= Fused flash attention =============================
// Per CTA: 128 q-rows of one (b,h), 8 warps. 64-key tiles double-buffered.
// Q hi/lo resident; K hi only; V hi only (ldmatrix.trans). 2-pass fp16.
// smem: Q 2*18432 + K 2*9216 + V 2*9216 = 73728.
#define FL_STRIDE 144
#define FL_Q      18432              // 128*144
#define FL_KV     9216               // 64*144
#define FL_KBASE  (2 * FL_Q)         // 36864
#define FL_VBASE  (FL_KBASE + 2 * FL_KV)  // 55296
#define FL_SMEM   (FL_VBASE + 2 * FL_KV)  // 73728

__global__ void __launch_bounds__(256) flash_kernel()
{
    extern __shared__ char smem[];
    const int tid = threadIdx.x, wid = tid >> 5, lane = tid & 31;
    const uint32_t sb = smem_u32(smem);
    const int z = blockIdx.y, b = z >> 4, h = z & 15;
    const int bm = blockIdx.x * 128;
    const int wm = wid * 16;

    const size_t qoff = (size_t)(b * SEQ + bm) * F3 + (size_t)h * HD;
    const __half* qhg = g_qkv_hi + qoff;
    const __half* qlg = g_qkv_lo + qoff;
    const size_t kbase = (size_t)b * SEQ * F3 + CDIM + (size_t)h * HD;
    const __half* khg = g_qkv_hi + kbase;
    const size_t vbase = (size_t)b * SEQ * F3 + 2 * CDIM + (size_t)h * HD;
    const __half* vhg = g_qkv_hi + vbase;

    const uint32_t SQH = sb, SQL = sb + FL_Q;

    // Q (group 0): 128 rows x 64 cols hi+lo = 2048 chunks
#pragma unroll
    for (int it = 0; it < 8; ++it) {
        int idx = tid + 256 * it;
        int mat = idx >> 10, r = (idx >> 3) & 127, c = idx & 7;
        uint32_t dst = (mat ? SQL : SQH) + (uint32_t)(r * FL_STRIDE + c * 16);
        const __half* src = (mat ? qlg : qhg) + (size_t)r * F3 + c * 8;
        CP16(dst, src);
    }
    CP_COMMIT();

    auto cp_k = [&](int buf, int key0) {
        uint32_t base = sb + FL_KBASE + (uint32_t)buf * FL_KV;
#pragma unroll
        for (int it = 0; it < 2; ++it) {
            int idx = tid + 256 * it;            // 0..511
            int r = idx >> 3, c = idx & 7;
            uint32_t dst = base + (uint32_t)(r * FL_STRIDE + c * 16);
            CP16(dst, khg + (size_t)(key0 + r) * F3 + c * 8);
        }
    };
    auto cp_v = [&](int buf, int key0) {
        uint32_t base = sb + FL_VBASE + (uint32_t)buf * FL_KV;
#pragma unroll
        for (int it = 0; it < 2; ++it) {
            int idx = tid + 256 * it;
            int r = idx >> 3, c = idx & 7;
            uint32_t dst = base + (uint32_t)(r * FL_STRIDE + c * 16);
            CP16(dst, vhg + (size_t)(key0 + r) * F3 + c * 8);
        }
    };

    cp_k(0, 0); cp_v(0, 0); CP_COMMIT();
    CP_WAIT1();                       // Q resident
    __syncthreads();

    // Q fragments (resident; pre-scaled into exp2 domain)
    uint32_t qh[4][4], ql[4][4];
    {
        const uint32_t arow = (uint32_t)((wm + (lane & 15)) * FL_STRIDE + (lane >> 4) * 16);
#pragma unroll
        for (int ks = 0; ks < 4; ++ks) {
            LDMX4(qh[ks][0], qh[ks][1], qh[ks][2], qh[ks][3], SQH + arow + ks * 32);
            LDMX4(ql[ks][0], ql[ks][1], ql[ks][2], ql[ks][3], SQL + arow + ks * 32);
        }
    }

    float acco[8][4];
#pragma unroll
    for (int j = 0; j < 8; ++j)
#pragma unroll
        for (int k = 0; k < 4; ++k) acco[j][k] = 0.0f;
    float mr0 = -1e30f, mr1 = -1e30f, lr0 = 0.0f, lr1 = 0.0f;

    const uint32_t boff = (uint32_t)((8 * (lane >> 4) + (lane & 7)) * FL_STRIDE
                                     + ((lane >> 3) & 1) * 16);
    const uint32_t voff = (uint32_t)(((((lane >> 3) & 1) * 8) + (lane & 7)) * FL_STRIDE
                                     + (lane >> 4) * 16);

    const int NT = SEQ / 64;  // 32
    for (int t = 0; t < NT; ++t) {
        const int bf = t & 1;
        if (t + 1 < NT) {
            cp_k(1 - bf, (t + 1) * 64);
            cp_v(1 - bf, (t + 1) * 64);
            CP_COMMIT();
            CP_WAIT1();
        } else {
            CP_WAIT0();
        }
        __syncthreads();

        // ---- S = Q @ K^T (2-pass: Qh*Kh + Ql*Kh); S in log2 units
        const uint32_t khb = sb + FL_KBASE + (uint32_t)bf * FL_KV;
        float accs[8][4];
#pragma unroll
        for (int j = 0; j < 8; ++j)
#pragma unroll
            for (int k = 0; k < 4; ++k) accs[j][k] = 0.0f;
#pragma unroll
        for (int ks = 0; ks < 4; ++ks) {
#pragma unroll
            for (int jp = 0; jp < 4; ++jp) {
                uint32_t off = boff + (uint32_t)(jp * 16 * FL_STRIDE + ks * 32);
                uint32_t h0, h1, h2, h3;
                LDMX4(h0, h1, h2, h3, khb + off);
                mma16816(accs[2*jp],   qh[ks][0], qh[ks][1], qh[ks][2], qh[ks][3], h0, h1);
                mma16816(accs[2*jp+1], qh[ks][0], qh[ks][1], qh[ks][2], qh[ks][3], h2, h3);
                mma16816(accs[2*jp],   ql[ks][0], ql[ks][1], ql[ks][2], ql[ks][3], h0, h1);
                mma16816(accs[2*jp+1], ql[ks][0], ql[ks][1], ql[ks][2], ql[ks][3], h2, h3);
            }
        }

        // ---- online softmax (exp2 domain)
        float rm0 = -1e30f, rm1 = -1e30f;
#pragma unroll
        for (int j = 0; j < 8; ++j) {
            rm0 = fmaxf(rm0, fmaxf(accs[j][0], accs[j][1]));
            rm1 = fmaxf(rm1, fmaxf(accs[j][2], accs[j][3]));
        }
        rm0 = fmaxf(rm0, __shfl_xor_sync(0xffffffffu, rm0, 1));
        rm0 = fmaxf(rm0, __shfl_xor_sync(0xffffffffu, rm0, 2));
        rm1 = fmaxf(rm1, __shfl_xor_sync(0xffffffffu, rm1, 1));
        rm1 = fmaxf(rm1, __shfl_xor_sync(0xffffffffu, rm1, 2));
        const float mn0 = fmaxf(mr0, rm0), mn1 = fmaxf(mr1, rm1);
        const float al0 = exp2f(mr0 - mn0), al1 = exp2f(mr1 - mn1);
        mr0 = mn0; mr1 = mn1;

        float s0 = 0.0f, s1 = 0.0f;
        uint32_t pah[4][4], pal[4][4];
#pragma unroll
        for (int j = 0; j < 8; ++j) {
            float p0 = exp2f(accs[j][0] - mn0);
            float p1 = exp2f(accs[j][1] - mn0);
            float p2 = exp2f(accs[j][2] - mn1);
            float p3 = exp2f(accs[j][3] - mn1);
            s0 += p0 + p1; s1 += p2 + p3;
            __half h0b, l0b, h1b, l1b, h2b, l2b, h3b, l3b;
            cvt_hilo(p0, h0b, l0b); cvt_hilo(p1, h1b, l1b);
            cvt_hilo(p2, h2b, l2b); cvt_hilo(p3, h3b, l3b);
            const int ks = j >> 1;
            if ((j & 1) == 0) {
                pah[ks][0] = pk(h0b, h1b); pah[ks][1] = pk(h2b, h3b);
                pal[ks][0] = pk(l0b, l1b); pal[ks][1] = pk(l2b, l3b);
            } else {
                pah[ks][2] = pk(h0b, h1b); pah[ks][3] = pk(h2b, h3b);
                pal[ks][2] = pk(l0b, l1b); pal[ks][3] = pk(l2b, l3b);
            }
        }
        s0 += __shfl_xor_sync(0xffffffffu, s0, 1);
        s0 += __shfl_xor_sync(0xffffffffu, s0, 2);
        s1 += __shfl_xor_sync(0xffffffffu, s1, 1);
        s1 += __shfl_xor_sync(0xffffffffu, s1, 2);
        lr0 = lr0 * al0 + s0; lr1 = lr1 * al1 + s1;
#pragma unroll
        for (int j = 0; j < 8; ++j) {
            acco[j][0] *= al0; acco[j][1] *= al0;
            acco[j][2] *= al1; acco[j][3] *= al1;
        }

        // ---- O += P @ V (2-pass: Ph*Vh + Pl*Vh); V via ldmatrix.trans
        const uint32_t vhb = sb + FL_VBASE + (uint32_t)bf * FL_KV;
#pragma unroll
        for (int ks = 0; ks < 4; ++ks) {
#pragma unroll
            for (int jp = 0; jp < 4; ++jp) {
                uint32_t off = voff + (uint32_t)(ks * 16 * FL_STRIDE + jp * 32);
                uint32_t h0, h1, h2, h3;
                LDMX4T(h0, h1, h2, h3, vhb + off);
                mma16816(acco[2*jp],   pah[ks][0], pah[ks][1], pah[ks][2], pah[ks][3], h0, h1);
                mma16816(acco[2*jp+1], pah[ks][0], pah[ks][1], pah[ks][2], pah[ks][3], h2, h3);
                mma16816(acco[2*jp],   pal[ks][0], pal[ks][1], pal[ks][2], pal[ks][3], h0, h1);
                mma16816(acco[2*jp+1], pal[ks][0], pal[ks][1], pal[ks][2], pal[ks][3], h2, h3);
            }
        }
        __syncthreads();
    }

    // ---- epilogue: O / l -> attn hi/lo
    const float inv0 = 1.0f / lr0, inv1 = 1.0f / lr1;
    const int rg = b * SEQ + bm + wm + (lane >> 2);
#pragma unroll
    for (int j = 0; j < 8; ++j) {
        const int col = h * HD + j * 8 + (lane & 3) * 2;
        __half h0b, l0b, h1b, l1b;
        cvt_hilo(acco[j][0] * inv0, h0b, l0b);
        cvt_hilo(acco[j][1] * inv0, h1b, l1b);
        size_t off = (size_t)rg * CDIM + col;
        *(uint32_t*)(g_attn_hi + off) = pk(h0b, h1b);
        *(uint32_t*)(g_attn_lo + off) = pk(l0b, l1b);
        cvt_hilo(acco[j][2] * inv1, h0b, l0b);
        cvt_hilo(acco[j][3] * inv1, h1b, l1b);
        off = (size_t)(rg + 8) * CDIM + col;
        *(uint32_t*)(g_attn_hi + off) = pk(h0b, h1b);
        *(uint32_t*)(g_attn_lo + off) = pk(l0b, l1b);
    }
}

// ---------------------------------------------------------------------------
// fp32 -> fp16 hi(/lo) elementwise convert
// ---------------------------------------------------------------------------
__global__ void __launch_bounds__(256) cvt_kernel(
    const float4* __restrict__ src, uint2* __restrict__ hi,
    uint2* __restrict__ lo, int n4)
{
    int i = blockIdx.x * blockDim.x + threadIdx.x;
    if (i >= n4) return;
    float4 v = src[i];
    __half h0, h1, h2, h3, l0, l1, l2, l3;
    cvt_hilo(v.x, h0, l0); cvt_hilo(v.y, h1, l1);
    cvt_hilo(v.z, h2, l2); cvt_hilo(v.w, h3, l3);
    hi[i] = make_uint2(pk(h0, h1), pk(h2, h3));
    if (lo) lo[i] = make_uint2(pk(l0, l1), pk(l2, l3));
}

// ---------------------------------------------------------------------------
extern "C" void kernel_launch(void* const* d_in, const int* in_sizes, int n_in,
                              void* d_out, int out_size)
{
    (void)in_sizes; (void)n_in; (void)out_size;
    const float* x     = (const float*)d_in[0];
    const float* w_qkv = (const float*)d_in[1];
    const float* w_out = (const float*)d_in[2];
    const float* b_out = (const float*)d_in[3];
    float* out = (float*)d_out;

    static int attr_done = 0;
    if (!attr_done) {
        cudaFuncSetAttribute(mma_gemm, cudaFuncAttributeMaxDynamicSharedMemorySize,
                             2 * GM_BUF);
        cudaFuncSetAttribute(flash_kernel, cudaFuncAttributeMaxDynamicSharedMemorySize,
                             FL_SMEM);
        attr_done = 1;
    }

    __half *xh, *xl, *qh, *oh;
    cudaGetSymbolAddress((void**)&xh, g_x_hi);
    cudaGetSymbolAddress((void**)&xl, g_x_lo);
    cudaGetSymbolAddress((void**)&qh, g_wqkv_hi);
    cudaGetSymbolAddress((void**)&oh, g_wout_hi);

    {
        int n4 = MROWS * CDIM / 4;
        cvt_kernel<<<(n4 + 255) / 256, 256>>>((const float4*)x, (uint2*)xh, (uint2*)xl, n4);
        n4 = F3 * CDIM / 4;
        cvt_kernel<<<(n4 + 255) / 256, 256>>>((const float4*)w_qkv, (uint2*)qh, nullptr, n4);
        n4 = CDIM * CDIM / 4;
        cvt_kernel<<<(n4 + 255) / 256, 256>>>((const float4*)w_out, (uint2*)oh, nullptr, n4);
    }

    // 1) QKV -> g_qkv hi(/lo for Q region); Q pre-scaled into exp2 domain
    mma_gemm<<<dim3(F3 / 256, MROWS / 128), 256, 2 * GM_BUF>>>(0, nullptr, nullptr);
    // 2) fused flash attention -> g_attn hi/lo
    flash_kernel<<<dim3(SEQ / 128, NBH), 256, FL_SMEM>>>();
    // 3) proj -> out (+bias)
    mma_gemm<<<dim3(CDIM / 256, MROWS / 128), 256, 2 * GM_BUF>>>(2, b_out, out);
}